// round 16
// baseline (speedup 1.0000x reference)
#include <cuda_runtime.h>
#include <cstddef>

// Hin2vec layer: B=262144, N=1e6, R=64, H=128.
// R15: persistent grid-stride warps; next iteration's indices (x,y,r,l int4s)
// are prefetched into a per-warp smem double-buffer via cp.async -> index
// DRAM latency hidden with ZERO persistent register cost (R6 register
// footprint, R7 latency hiding, no launch_bounds cap => no spills).

#define H_DIM 128
#define R_DIM 64
#define WPB   8      // warps per block
#define ELEMS 4      // elements per warp-iteration
#define NBLOCKS (148 * 5)

__device__ float d_reWr[R_DIM * H_DIM];   // 32 KB: s*(1-s) of clamp(Wr)

__global__ void hin_prep(const float* __restrict__ Wr, float* __restrict__ loss_ptr) {
    const int t = blockIdx.x * blockDim.x + threadIdx.x;
    if (t < R_DIM * H_DIM) {
        float e = fminf(fmaxf(Wr[t], -6.0f), 6.0f);
        float s = 1.0f / (1.0f + __expf(-e));
        d_reWr[t] = s * (1.0f - s);
    }
    if (t == 0 && loss_ptr) *loss_ptr = 0.0f;
}

// Predicated 16B cp.async (L1-cached: consecutive warps' slots share lines).
__device__ __forceinline__ void cp16ca(void* smem_dst, const void* gsrc, bool pred) {
    unsigned saddr = (unsigned)__cvta_generic_to_shared(smem_dst);
    asm volatile(
        "{\n\t"
        ".reg .pred p;\n\t"
        "setp.ne.b32 p, %0, 0;\n\t"
        "@p cp.async.ca.shared.global [%1], [%2], 16;\n\t"
        "}"
        :: "r"((int)pred), "r"(saddr), "l"(gsrc));
}

__device__ __forceinline__ float dot_rw(float4 a, float4 b, float4 w) {
    float acc = a.x * b.x * w.x;
    acc = fmaf(a.y * b.y, w.y, acc);
    acc = fmaf(a.z * b.z, w.z, acc);
    acc = fmaf(a.w * b.w, w.w, acc);
    return acc;
}

__global__ void __launch_bounds__(WPB * 32)
hin_main(const int* __restrict__ x,
         const int* __restrict__ y,
         const int* __restrict__ r,
         const int* __restrict__ l,
         const float4* __restrict__ Wx,   // [N, H/4]
         float* __restrict__ out,         // [B, 2] logits
         float* __restrict__ loss_out,    // scalar (may be null)
         int B, float invB)
{
    // Per-warp double-buffered index slots: [warp][buf][x,y,r,l] int4s.
    __shared__ int4  islot[WPB][2][4];
    __shared__ float sloss[WPB];

    const int wid    = threadIdx.x >> 5;
    const int lane   = threadIdx.x & 31;
    const int nwarps = gridDim.x * WPB;
    const int nchunk = B >> 2;                 // B % 4 == 0

    float loss_acc = 0.0f;

    int chunk = blockIdx.x * WPB + wid;
    int buf   = 0;

    // Prologue: prefetch indices for the first chunk into buf 0.
    if (lane < 4) {
        const int* src = (lane == 0) ? x : (lane == 1) ? y : (lane == 2) ? r : l;
        cp16ca(&islot[wid][0][lane], src + chunk * ELEMS, chunk < nchunk);
    }
    asm volatile("cp.async.commit_group;");

    while (chunk < nchunk) {
        // Index slot ready (prefetched >=1 iteration ago; first time ~L2 hit).
        asm volatile("cp.async.wait_group 0;");
        __syncwarp();

        const int4 xv = islot[wid][buf][0];
        const int4 yv = islot[wid][buf][1];
        const int4 rv = islot[wid][buf][2];

        // Issue all 8 random 512B gathers immediately (MLP=8, L2-only hint).
        const float4 ax0 = __ldcg(Wx + (unsigned)xv.x * (H_DIM / 4) + lane);
        const float4 ay0 = __ldcg(Wx + (unsigned)yv.x * (H_DIM / 4) + lane);
        const float4 ax1 = __ldcg(Wx + (unsigned)xv.y * (H_DIM / 4) + lane);
        const float4 ay1 = __ldcg(Wx + (unsigned)yv.y * (H_DIM / 4) + lane);
        const float4 ax2 = __ldcg(Wx + (unsigned)xv.z * (H_DIM / 4) + lane);
        const float4 ay2 = __ldcg(Wx + (unsigned)yv.z * (H_DIM / 4) + lane);
        const float4 ax3 = __ldcg(Wx + (unsigned)xv.w * (H_DIM / 4) + lane);
        const float4 ay3 = __ldcg(Wx + (unsigned)yv.w * (H_DIM / 4) + lane);

        // Prefetch next chunk's indices into the other buffer (registers free
        // immediately; completion checked at next iteration's wait).
        const int next = chunk + nwarps;
        if (lane < 4) {
            const int* src = (lane == 0) ? x : (lane == 1) ? y : (lane == 2) ? r : l;
            cp16ca(&islot[wid][buf ^ 1][lane], src + next * ELEMS, next < nchunk);
        }
        asm volatile("cp.async.commit_group;");

        // Regularization rows from the hot 32KB L1-resident table.
        const float4* RW = (const float4*)d_reWr;
        const float4 rw0 = __ldg(RW + (unsigned)rv.x * (H_DIM / 4) + lane);
        const float4 rw1 = __ldg(RW + (unsigned)rv.y * (H_DIM / 4) + lane);
        const float4 rw2 = __ldg(RW + (unsigned)rv.z * (H_DIM / 4) + lane);
        const float4 rw3 = __ldg(RW + (unsigned)rv.w * (H_DIM / 4) + lane);

        float a0 = dot_rw(ax0, ay0, rw0);
        float a1 = dot_rw(ax1, ay1, rw1);
        float a2 = dot_rw(ax2, ay2, rw2);
        float a3 = dot_rw(ax3, ay3, rw3);

        // Four interleaved butterfly reductions.
        #pragma unroll
        for (int o = 16; o > 0; o >>= 1) {
            a0 += __shfl_xor_sync(0xFFFFFFFFu, a0, o);
            a1 += __shfl_xor_sync(0xFFFFFFFFu, a1, o);
            a2 += __shfl_xor_sync(0xFFFFFFFFu, a2, o);
            a3 += __shfl_xor_sync(0xFFFFFFFFu, a3, o);
        }

        // Lanes 0..3 each finish one element.
        if (lane < ELEMS) {
            const float acc = (lane == 0) ? a0 : (lane == 1) ? a1 : (lane == 2) ? a2 : a3;
            const float p = 1.0f / (1.0f + __expf(-acc));
            const int base = chunk * ELEMS;

            float2 lg;                       // streaming store, written once
            lg.x = p;
            lg.y = 1.0f - p;
            __stcs(reinterpret_cast<float2*>(out) + base + lane, lg);

            if (loss_out) {
                const float ea  = __expf(p);
                const float eb  = __expf(1.0f - p);
                const float lse = __logf(ea + eb);
                const int   li  = ((const int*)&islot[wid][buf][3])[lane];  // prefetched l
                const float chosen = (li == 0) ? p : (1.0f - p);
                loss_acc += (lse - chosen) * invB;
            }
        }

        chunk = next;
        buf ^= 1;
    }

    if (loss_out) {
        // Fold lanes 0..3 partials; other lanes hold 0.
        loss_acc += __shfl_xor_sync(0xFFFFFFFFu, loss_acc, 1);
        loss_acc += __shfl_xor_sync(0xFFFFFFFFu, loss_acc, 2);
        if (lane == 0) sloss[wid] = loss_acc;
        __syncthreads();
        if (threadIdx.x == 0) {
            float s = 0.0f;
            #pragma unroll
            for (int w = 0; w < WPB; w++) s += sloss[w];
            atomicAdd(loss_out, s);
        }
    }
}

extern "C" void kernel_launch(void* const* d_in, const int* in_sizes, int n_in,
                              void* d_out, int out_size)
{
    const int*    x  = (const int*)d_in[0];
    const int*    y  = (const int*)d_in[1];
    const int*    r  = (const int*)d_in[2];
    const int*    l  = (const int*)d_in[3];
    const float4* Wx = (const float4*)d_in[4];
    const float*  Wr = (const float*)d_in[5];

    const int B = in_sizes[0];
    float* out = (float*)d_out;
    float* loss_ptr = (out_size > 2 * B) ? (out + 2 * B) : nullptr;

    hin_prep<<<(R_DIM * H_DIM + 255) / 256, 256>>>(Wr, loss_ptr);

    hin_main<<<NBLOCKS, WPB * 32>>>(
        x, y, r, l, Wx, out, loss_ptr, B, 1.0f / (float)B);
}